// round 4
// baseline (speedup 1.0000x reference)
#include <cuda_runtime.h>
#include <cstdint>

// ---------------------------------------------------------------------------
// FocDecoderRNN — TF32 tensor cores; GRU fused into GEMM epilogue.
//   gi2 = patch @ (w_ih2 @ e2w)^T + (b_ih2 + w_ih2 @ e2b)    (K: 256 -> 64)
//   gemm_gru computes all 3 gates for a 128x64 slice and applies the GRU
//   in-register -> h written straight to out. No gi buffers, no gru kernels.
// ---------------------------------------------------------------------------

#define BSZ  2048
#define MAXK 64

__device__ float d_xp [4 * BSZ * 256];
__device__ float d_x1 [BSZ * 256];
__device__ float d_gh1[BSZ * 768];
__device__ float d_gh2[BSZ * 768];
__device__ float d_o1 [BSZ * 64];
__device__ float d_o2 [(size_t)MAXK * BSZ * 64];
__device__ float d_w2p[768 * 64];
__device__ float d_b2p[768];
__device__ int   d_cx[MAXK], d_cy[MAXK], d_cmap[64];

// ---------------------------------------------------------------------------
__global__ void find_cells_kernel(const float* __restrict__ fa,
                                  int* __restrict__ cx, int* __restrict__ cy,
                                  int* __restrict__ cmap)
{
    if (threadIdx.x == 0 && blockIdx.x == 0) {
        for (int i = 0; i < 64; i++) cmap[i] = -1;
        int k = 0;
        for (int i = 0; i < 8; i++)
            for (int j = 0; j < 8; j++)
                if (fa[i * 8 + j] > 0.5f) { cx[k] = i; cy[k] = j; cmap[i * 8 + j] = k; k++; }
    }
}

__global__ void compose_w2_kernel(const float* __restrict__ wih2,
                                  const float* __restrict__ e2w,
                                  const float* __restrict__ e2b,
                                  const float* __restrict__ bih2,
                                  float* __restrict__ W2p, float* __restrict__ b2p)
{
    const int n = blockIdx.x;      // 0..767
    const int t = threadIdx.x;     // 0..63
    float s = 0.f;
    for (int c = 0; c < 256; c++)
        s += wih2[n * 256 + c] * e2w[c * 64 + t];
    W2p[n * 64 + t] = s;
    if (t == 0) {
        float sb = 0.f;
        for (int c = 0; c < 256; c++) sb += wih2[n * 256 + c] * e2b[c];
        b2p[n] = bih2[n] + sb;
    }
}

// ---------------------------------------------------------------------------
__device__ __forceinline__ uint32_t f2tf32(float x)
{
    uint32_t u;
    asm("cvt.rna.tf32.f32 %0, %1;" : "=r"(u) : "f"(x));
    return u;
}

__device__ __forceinline__ void mma_tf32(float c[4], const uint32_t a[4], const uint32_t b[2])
{
    asm volatile(
        "mma.sync.aligned.m16n8k8.row.col.f32.tf32.tf32.f32 "
        "{%0,%1,%2,%3},{%4,%5,%6,%7},{%8,%9},{%0,%1,%2,%3};\n"
        : "+f"(c[0]), "+f"(c[1]), "+f"(c[2]), "+f"(c[3])
        : "r"(a[0]), "r"(a[1]), "r"(a[2]), "r"(a[3]), "r"(b[0]), "r"(b[1]));
}

__device__ __forceinline__ float sigf(float x) { return 1.f / (1.f + __expf(-x)); }

// ---------------------------------------------------------------------------
// Plain double-buffered TF32 GEMM-NT (from R3): C[z] = A[z] @ Bw[z]^T (+bias)
template<int NT, int AMODE>
__global__ __launch_bounds__(256)
void gemm_tc(const float* __restrict__ A, const float* __restrict__ Bw,
             const float* __restrict__ bias, float* __restrict__ C,
             int M, int N, int K, int lda, int ldb,
             long long sAz, long long sBz, long long sCz,
             const int* __restrict__ cxs, const int* __restrict__ cys)
{
    constexpr int WN  = (NT == 128) ? 4 : 2;
    constexpr int MF  = (NT == 128) ? 4 : 2;
    constexpr int NF  = 4;
    constexpr int WMS = MF * 16;
    constexpr int BLD = (NT == 128) ? 8 : 4;

    __shared__ uint32_t As[2][128][20];
    __shared__ uint32_t Bs[2][NT][20];

    const int bm = blockIdx.y * 128;
    const int bn = blockIdx.x * NT;
    int cellx = 0, celly = 0;
    if (AMODE == 1) { cellx = cxs[blockIdx.z]; celly = cys[blockIdx.z]; }
    if (AMODE == 0) A += (long long)blockIdx.z * sAz;
    Bw += (long long)blockIdx.z * sBz;
    C  += (long long)blockIdx.z * sCz;

    const int tid  = threadIdx.x;
    const int lane = tid & 31;
    const int wid  = tid >> 5;
    const int wm   = wid / WN;
    const int wn   = wid % WN;
    const int g    = lane >> 2;
    const int t    = lane & 3;
    const int ar   = tid >> 1;
    const int ac   = (tid & 1) * 8;
    const int br   = (NT == 128) ? (tid >> 1) : (tid >> 2);
    const int bc   = (NT == 128) ? (tid & 1) * 8 : (tid & 3) * 4;

    float acc[MF][NF][4];
#pragma unroll
    for (int i = 0; i < MF; i++)
#pragma unroll
        for (int j = 0; j < NF; j++)
#pragma unroll
            for (int q = 0; q < 4; q++) acc[i][j][q] = 0.f;

    float a_pref[8], b_pref[BLD];
    {
        const float* ap;
        if (AMODE == 0) ap = A + (long long)(bm + ar) * lda + ac;
        else            ap = A + (long long)(bm + ar) * 4096 + cellx * 512 + ((ac >> 3) << 6) + celly * 8;
        const float4 v0 = *reinterpret_cast<const float4*>(ap);
        const float4 v1 = *reinterpret_cast<const float4*>(ap + 4);
        a_pref[0]=v0.x; a_pref[1]=v0.y; a_pref[2]=v0.z; a_pref[3]=v0.w;
        a_pref[4]=v1.x; a_pref[5]=v1.y; a_pref[6]=v1.z; a_pref[7]=v1.w;
        const float* bp = Bw + (long long)(bn + br) * ldb + bc;
        const float4 w0 = *reinterpret_cast<const float4*>(bp);
        b_pref[0]=w0.x; b_pref[1]=w0.y; b_pref[2]=w0.z; b_pref[3]=w0.w;
        if (BLD == 8) {
            const float4 w1 = *reinterpret_cast<const float4*>(bp + 4);
            b_pref[4]=w1.x; b_pref[5]=w1.y; b_pref[6]=w1.z; b_pref[7]=w1.w;
        }
    }
#pragma unroll
    for (int q = 0; q < 8; q++)   As[0][ar][ac + q] = f2tf32(a_pref[q]);
#pragma unroll
    for (int q = 0; q < BLD; q++) Bs[0][br][bc + q] = f2tf32(b_pref[q]);
    __syncthreads();

    const int nIter = K >> 4;
    for (int it = 0; it < nIter; it++) {
        const int cur = it & 1;
        const bool more = (it + 1 < nIter);
        if (more) {
            const int k0 = (it + 1) * 16;
            const float* ap;
            if (AMODE == 0) ap = A + (long long)(bm + ar) * lda + k0 + ac;
            else { const int tt = k0 + ac;
                   ap = A + (long long)(bm + ar) * 4096 + cellx * 512 + ((tt >> 3) << 6) + celly * 8; }
            const float4 v0 = *reinterpret_cast<const float4*>(ap);
            const float4 v1 = *reinterpret_cast<const float4*>(ap + 4);
            a_pref[0]=v0.x; a_pref[1]=v0.y; a_pref[2]=v0.z; a_pref[3]=v0.w;
            a_pref[4]=v1.x; a_pref[5]=v1.y; a_pref[6]=v1.z; a_pref[7]=v1.w;
            const float* bp = Bw + (long long)(bn + br) * ldb + k0 + bc;
            const float4 w0 = *reinterpret_cast<const float4*>(bp);
            b_pref[0]=w0.x; b_pref[1]=w0.y; b_pref[2]=w0.z; b_pref[3]=w0.w;
            if (BLD == 8) {
                const float4 w1 = *reinterpret_cast<const float4*>(bp + 4);
                b_pref[4]=w1.x; b_pref[5]=w1.y; b_pref[6]=w1.z; b_pref[7]=w1.w;
            }
        }
#pragma unroll
        for (int kk = 0; kk < 16; kk += 8) {
            uint32_t af[MF][4], bf[NF][2];
#pragma unroll
            for (int i = 0; i < MF; i++) {
                const int m = wm * WMS + i * 16;
                af[i][0] = As[cur][m + g][kk + t];
                af[i][1] = As[cur][m + 8 + g][kk + t];
                af[i][2] = As[cur][m + g][kk + t + 4];
                af[i][3] = As[cur][m + 8 + g][kk + t + 4];
            }
#pragma unroll
            for (int j = 0; j < NF; j++) {
                const int n = wn * 32 + j * 8;
                bf[j][0] = Bs[cur][n + g][kk + t];
                bf[j][1] = Bs[cur][n + g][kk + t + 4];
            }
#pragma unroll
            for (int i = 0; i < MF; i++)
#pragma unroll
                for (int j = 0; j < NF; j++) mma_tf32(acc[i][j], af[i], bf[j]);
        }
        if (more) {
            const int nxt = cur ^ 1;
#pragma unroll
            for (int q = 0; q < 8; q++)   As[nxt][ar][ac + q] = f2tf32(a_pref[q]);
#pragma unroll
            for (int q = 0; q < BLD; q++) Bs[nxt][br][bc + q] = f2tf32(b_pref[q]);
            __syncthreads();
        }
    }

#pragma unroll
    for (int i = 0; i < MF; i++) {
        const int row0 = bm + wm * WMS + i * 16 + g;
#pragma unroll
        for (int j = 0; j < NF; j++) {
            const int col = bn + wn * 32 + j * 8 + 2 * t;
            float bz0 = 0.f, bz1 = 0.f;
            if (bias) { bz0 = __ldg(&bias[col]); bz1 = __ldg(&bias[col + 1]); }
            *reinterpret_cast<float2*>(&C[(long long)row0 * N + col]) =
                make_float2(acc[i][j][0] + bz0, acc[i][j][1] + bz1);
            *reinterpret_cast<float2*>(&C[(long long)(row0 + 8) * N + col]) =
                make_float2(acc[i][j][2] + bz0, acc[i][j][3] + bz1);
        }
    }
}

// ---------------------------------------------------------------------------
// Fused GEMM+GRU.  For gate-column slice [bn, bn+64) of H=256 and batch rows
// [bm, bm+128): computes gi_g = A @ W[g*256+bn .. ]^T + bias for g=r,z,n in
// 3 accumulator sets, then h' = (1-z)*tanh(in + r*hn) + z*h0 in-register.
//   AMODE 0: A normal (lda).  AMODE 1: A = patch gather from x (K=64).
// gh: (B,768) precomputed h-gate buffer (bias included). hout: (B,256) + z*sHz.
// K-slab 8, double buffered. smem pad 12 (bank-clean for stride-12 reads).
template<int AMODE>
__global__ __launch_bounds__(256)
void gemm_gru(const float* __restrict__ A, const float* __restrict__ Bw,
              const float* __restrict__ bias, const float* __restrict__ gh,
              const float* __restrict__ h0, float* __restrict__ hout,
              int K, int lda, long long sHz,
              const int* __restrict__ cxs, const int* __restrict__ cys)
{
    __shared__ uint32_t As[2][128][12];
    __shared__ uint32_t Bs[2][192][12];

    const int bm = blockIdx.y * 128;
    const int bn = blockIdx.x * 64;        // gate-column offset in [0,256)
    int cellx = 0, celly = 0;
    if (AMODE == 1) { cellx = cxs[blockIdx.z]; celly = cys[blockIdx.z]; }
    hout += (long long)blockIdx.z * sHz;

    const int tid  = threadIdx.x;
    const int lane = tid & 31;
    const int wid  = tid >> 5;
    const int wm   = wid >> 1;             // 0..3
    const int wn   = wid & 1;              // 0..1
    const int g    = lane >> 2;
    const int t    = lane & 3;
    const int ar   = tid >> 1;             // A: 0..127
    const int ac   = (tid & 1) * 4;        // A col 0/4
    const int bgate = tid >> 6;            // B: tid<192 -> gate 0..2
    const int brow  = tid & 63;            //     row within gate

    float acc[3][2][4][4];
#pragma unroll
    for (int gg = 0; gg < 3; gg++)
#pragma unroll
        for (int i = 0; i < 2; i++)
#pragma unroll
            for (int j = 0; j < 4; j++)
#pragma unroll
                for (int q = 0; q < 4; q++) acc[gg][i][j][q] = 0.f;

    float a_pref[4], b_pref[8];
    const bool bload = (tid < 192);

    auto loadA = [&](int k0) {
        const float* ap;
        if (AMODE == 0) ap = A + (long long)(bm + ar) * lda + k0 + ac;
        else { const int tt = k0 + ac;
               ap = A + (long long)(bm + ar) * 4096 + cellx * 512 + ((tt >> 3) << 6) + celly * 8 + (tt & 7); }
        const float4 v = *reinterpret_cast<const float4*>(ap);
        a_pref[0]=v.x; a_pref[1]=v.y; a_pref[2]=v.z; a_pref[3]=v.w;
    };
    auto loadB = [&](int k0) {
        if (!bload) return;
        const float* bp = Bw + (long long)(bgate * 256 + bn + brow) * K + k0;
        const float4 w0 = *reinterpret_cast<const float4*>(bp);
        const float4 w1 = *reinterpret_cast<const float4*>(bp + 4);
        b_pref[0]=w0.x; b_pref[1]=w0.y; b_pref[2]=w0.z; b_pref[3]=w0.w;
        b_pref[4]=w1.x; b_pref[5]=w1.y; b_pref[6]=w1.z; b_pref[7]=w1.w;
    };
    auto stash = [&](int buf) {
#pragma unroll
        for (int q = 0; q < 4; q++) As[buf][ar][ac + q] = f2tf32(a_pref[q]);
        if (bload) {
#pragma unroll
            for (int q = 0; q < 8; q++) Bs[buf][bgate * 64 + brow][q] = f2tf32(b_pref[q]);
        }
    };

    loadA(0); loadB(0); stash(0);
    __syncthreads();

    const int nIter = K >> 3;
    for (int it = 0; it < nIter; it++) {
        const int cur = it & 1;
        const bool more = (it + 1 < nIter);
        if (more) { loadA((it + 1) * 8); loadB((it + 1) * 8); }

        uint32_t af[2][4];
#pragma unroll
        for (int i = 0; i < 2; i++) {
            const int m = wm * 32 + i * 16;
            af[i][0] = As[cur][m + g][t];
            af[i][1] = As[cur][m + 8 + g][t];
            af[i][2] = As[cur][m + g][t + 4];
            af[i][3] = As[cur][m + 8 + g][t + 4];
        }
#pragma unroll
        for (int gg = 0; gg < 3; gg++) {
            uint32_t bf[4][2];
#pragma unroll
            for (int j = 0; j < 4; j++) {
                const int n = gg * 64 + wn * 32 + j * 8;
                bf[j][0] = Bs[cur][n + g][t];
                bf[j][1] = Bs[cur][n + g][t + 4];
            }
#pragma unroll
            for (int i = 0; i < 2; i++)
#pragma unroll
                for (int j = 0; j < 4; j++) mma_tf32(acc[gg][i][j], af[i], bf[j]);
        }
        if (more) { stash(cur ^ 1); __syncthreads(); }
    }

    // ---- fused GRU epilogue ----
#pragma unroll
    for (int i = 0; i < 2; i++) {
        const int row0 = bm + wm * 32 + i * 16 + g;
#pragma unroll
        for (int j = 0; j < 4; j++) {
            const int col = bn + wn * 32 + j * 8 + 2 * t;       // in [0,256)
            const float2 br_ = *reinterpret_cast<const float2*>(&bias[col]);
            const float2 bz_ = *reinterpret_cast<const float2*>(&bias[256 + col]);
            const float2 bn_ = *reinterpret_cast<const float2*>(&bias[512 + col]);
#pragma unroll
            for (int half = 0; half < 2; half++) {
                const int row = row0 + half * 8;
                const int q0 = half * 2;
                const float* ghp = gh + (long long)row * 768 + col;
                const float2 hr = *reinterpret_cast<const float2*>(ghp);
                const float2 hz = *reinterpret_cast<const float2*>(ghp + 256);
                const float2 hn = *reinterpret_cast<const float2*>(ghp + 512);
                const float2 hv = *reinterpret_cast<const float2*>(&h0[(long long)row * 256 + col]);
                float2 o;
                {
                    const float r = sigf(acc[0][i][j][q0]     + br_.x + hr.x);
                    const float z = sigf(acc[1][i][j][q0]     + bz_.x + hz.x);
                    const float n = tanhf(acc[2][i][j][q0]    + bn_.x + r * hn.x);
                    o.x = (1.f - z) * n + z * hv.x;
                }
                {
                    const float r = sigf(acc[0][i][j][q0 + 1] + br_.y + hr.y);
                    const float z = sigf(acc[1][i][j][q0 + 1] + bz_.y + hz.y);
                    const float n = tanhf(acc[2][i][j][q0 + 1] + bn_.y + r * hn.y);
                    o.y = (1.f - z) * n + z * hv.y;
                }
                *reinterpret_cast<float2*>(&hout[(long long)row * 256 + col]) = o;
            }
        }
    }
}

// ---------------------------------------------------------------------------
__global__ void reduce_x1_kernel(const float* __restrict__ P, const float* __restrict__ bias,
                                 float* __restrict__ x1, int n4)
{
    const int idx = blockIdx.x * blockDim.x + threadIdx.x;
    if (idx >= n4) return;
    const float4 p0 = *reinterpret_cast<const float4*>(P + (size_t)0 * BSZ * 256 + idx * 4);
    const float4 p1 = *reinterpret_cast<const float4*>(P + (size_t)1 * BSZ * 256 + idx * 4);
    const float4 p2 = *reinterpret_cast<const float4*>(P + (size_t)2 * BSZ * 256 + idx * 4);
    const float4 p3 = *reinterpret_cast<const float4*>(P + (size_t)3 * BSZ * 256 + idx * 4);
    const int j0 = (idx * 4) & 255;
    const float4 b = *reinterpret_cast<const float4*>(bias + j0);
    float4 r;
    r.x = p0.x + p1.x + p2.x + p3.x + b.x;
    r.y = p0.y + p1.y + p2.y + p3.y + b.y;
    r.z = p0.z + p1.z + p2.z + p3.z + b.z;
    r.w = p0.w + p1.w + p2.w + p3.w + b.w;
    *reinterpret_cast<float4*>(x1 + idx * 4) = r;
}

// ---------------------------------------------------------------------------
__global__ void assemble_y_kernel(const float* __restrict__ o1, const float* __restrict__ o2,
                                  const int* __restrict__ cmap, float* __restrict__ y, int n4)
{
    const int idx = blockIdx.x * blockDim.x + threadIdx.x;   // over B*1024
    if (idx >= n4) return;
    const int b   = idx >> 10;
    const int rem = idx & 1023;
    const int i   = rem >> 4;            // 0..63
    const int j0  = (rem & 15) * 4;      // 0..60
    const float v = __ldg(&o1[b * 64 + i]);
    float4 r = make_float4(v, v, v, v);
    const int k = cmap[(i >> 3) * 8 + (j0 >> 3)];
    if (k >= 0) {
        const int t = (i & 7) * 8 + (j0 & 7);
        const float4 a = *reinterpret_cast<const float4*>(o2 + ((long long)k * BSZ + b) * 64 + t);
        r.x += a.x; r.y += a.y; r.z += a.z; r.w += a.w;
    }
    *reinterpret_cast<float4*>(y + (long long)idx * 4) = r;
}

// ---------------------------------------------------------------------------
extern "C" void kernel_launch(void* const* d_in, const int* in_sizes, int n_in,
                              void* d_out, int out_size)
{
    const float* x    = (const float*)d_in[0];
    const float* h    = (const float*)d_in[1];
    const float* fa   = (const float*)d_in[2];
    const float* e1w  = (const float*)d_in[3];
    const float* e1b  = (const float*)d_in[4];
    const float* wih1 = (const float*)d_in[5];
    const float* whh1 = (const float*)d_in[6];
    const float* bih1 = (const float*)d_in[7];
    const float* bhh1 = (const float*)d_in[8];
    const float* o1w  = (const float*)d_in[9];
    const float* o1b  = (const float*)d_in[10];
    const float* e2w  = (const float*)d_in[11];
    const float* e2b  = (const float*)d_in[12];
    const float* wih2 = (const float*)d_in[13];
    const float* whh2 = (const float*)d_in[14];
    const float* bih2 = (const float*)d_in[15];
    const float* bhh2 = (const float*)d_in[16];
    const float* o2w  = (const float*)d_in[17];
    const float* o2b  = (const float*)d_in[18];
    float* out = (float*)d_out;

    const int B = in_sizes[0] / 4096;                  // 2048
    const long long YOFF = (long long)B * 4096;
    int Kc = (int)(((long long)out_size - YOFF) / ((long long)B * 256)) - 1;
    if (Kc < 0) Kc = 0;
    if (Kc > MAXK) Kc = MAXK;

    float *p_xp, *p_x1, *p_gh1, *p_gh2, *p_o1, *p_o2, *p_w2p, *p_b2p;
    int *p_cx, *p_cy, *p_cmap;
    cudaGetSymbolAddress((void**)&p_xp,   d_xp);
    cudaGetSymbolAddress((void**)&p_x1,   d_x1);
    cudaGetSymbolAddress((void**)&p_gh1,  d_gh1);
    cudaGetSymbolAddress((void**)&p_gh2,  d_gh2);
    cudaGetSymbolAddress((void**)&p_o1,   d_o1);
    cudaGetSymbolAddress((void**)&p_o2,   d_o2);
    cudaGetSymbolAddress((void**)&p_w2p,  d_w2p);
    cudaGetSymbolAddress((void**)&p_b2p,  d_b2p);
    cudaGetSymbolAddress((void**)&p_cx,   d_cx);
    cudaGetSymbolAddress((void**)&p_cy,   d_cy);
    cudaGetSymbolAddress((void**)&p_cmap, d_cmap);

    float* yh0 = out + YOFF;                           // h1 slot
    float* yh2 = out + YOFF + (long long)B * 256;      // h2 slots

    find_cells_kernel<<<1, 32>>>(fa, p_cx, p_cy, p_cmap);
    compose_w2_kernel<<<768, 64>>>(wih2, e2w, e2b, bih2, p_w2p, p_b2p);

    // x1 split-K=4 partials (N=256, K slab=1024) + deterministic reduce
    gemm_tc<128, 0><<<dim3(2, B / 128, 4), 256>>>(x, e1w, nullptr, p_xp,
                                                  B, 256, 1024, 4096, 4096,
                                                  1024, 1024, (long long)B * 256,
                                                  nullptr, nullptr);
    reduce_x1_kernel<<<(B * 64 + 255) / 256, 256>>>(p_xp, e1b, p_x1, B * 64);

    // gh1, gh2 (N=768, K=256); bias = bhh -> gh buffers carry h-gate + bias
    gemm_tc<128, 0><<<dim3(6, B / 128), 256>>>(h, whh1, bhh1, p_gh1,
                                               B, 768, 256, 256, 256, 0, 0, 0, nullptr, nullptr);
    gemm_tc<128, 0><<<dim3(6, B / 128), 256>>>(h, whh2, bhh2, p_gh2,
                                               B, 768, 256, 256, 256, 0, 0, 0, nullptr, nullptr);

    // h1 = GRU(x1 @ wih1^T + b, gh1, h) -> out y_h[0]   (fused)
    gemm_gru<0><<<dim3(4, B / 128), 256>>>(p_x1, wih1, bih1, p_gh1, h, yh0,
                                           256, 256, 0, nullptr, nullptr);
    // o1 = h1 @ o1w^T + b  (N=64, K=256)
    gemm_tc<64, 0><<<dim3(1, B / 128), 256>>>(yh0, o1w, o1b, p_o1,
                                              B, 64, 256, 256, 256, 0, 0, 0, nullptr, nullptr);

    if (Kc > 0) {
        // h2[k] = GRU(patch[k] @ W2p^T + b2p, gh2, h) -> out y_h[1+k]  (fused)
        gemm_gru<1><<<dim3(4, B / 128, Kc), 256>>>(x, p_w2p, p_b2p, p_gh2, h, yh2,
                                                   64, 64, (long long)B * 256, p_cx, p_cy);
        // o2[k] = h2[k] @ o2w^T + b  (N=64, K=256)
        gemm_tc<64, 0><<<dim3(1, B / 128, Kc), 256>>>(yh2, o2w, o2b, p_o2,
                                                      B, 64, 256, 256, 256,
                                                      (long long)B * 256, 0, (long long)B * 64,
                                                      nullptr, nullptr);
    }
    // y = bcast(o1) + scatter(o2)
    assemble_y_kernel<<<(B * 1024 + 255) / 256, 256>>>(p_o1, p_o2, p_cmap, out, B * 1024);
}

// round 5
// speedup vs baseline: 1.8642x; 1.8642x over previous
#include <cuda_runtime.h>
#include <cstdint>

// ---------------------------------------------------------------------------
// FocDecoderRNN — R3 structure + cp.async 3-stage TF32 GEMM engine.
//   - Big GEMMs (x1 splitK, gh12 merged, gi1, gi2-gather) use gemm_ca:
//     cp.async pipelined, inputs pre-rounded to tf32 (rna) so raw loads are
//     bit-identical to the R3 cvt path.
//   - o1/o2 GEMMs keep the R3 register-cvt engine (A = exact fp32 from out).
//   - GRU/assemble/reduce kernels unchanged from R3.
// ---------------------------------------------------------------------------

#define BSZ  2048
#define MAXK 64

__device__ float d_xc  [(size_t)BSZ * 4096];     // tf32-rounded x
__device__ float d_hc  [BSZ * 256];              // tf32-rounded h
__device__ float d_e1c [256 * 4096];             // tf32-rounded embed1_w
__device__ float d_wi1c[768 * 256];              // tf32-rounded w_ih1
__device__ float d_whhc[1536 * 256];             // tf32-rounded [whh1;whh2]
__device__ float d_bhh [1536];                   // exact [bhh1;bhh2]
__device__ float d_xp  [4 * BSZ * 256];
__device__ float d_x1  [BSZ * 256];              // tf32-rounded
__device__ float d_gh12[(size_t)BSZ * 1536];
__device__ float d_gi1 [BSZ * 768];
__device__ float d_gi2 [(size_t)MAXK * BSZ * 768];
__device__ float d_o1  [BSZ * 64];
__device__ float d_o2  [(size_t)MAXK * BSZ * 64];
__device__ float d_w2p [768 * 64];               // tf32-rounded
__device__ float d_b2p [768];                    // exact
__device__ int   d_cx[MAXK], d_cy[MAXK], d_cmap[64];

// ---------------------------------------------------------------------------
__device__ __forceinline__ uint32_t f2tf32(float x)
{
    uint32_t u;
    asm("cvt.rna.tf32.f32 %0, %1;" : "=r"(u) : "f"(x));
    return u;
}

__device__ __forceinline__ void mma_tf32(float c[4], const uint32_t a[4], const uint32_t b[2])
{
    asm volatile(
        "mma.sync.aligned.m16n8k8.row.col.f32.tf32.tf32.f32 "
        "{%0,%1,%2,%3},{%4,%5,%6,%7},{%8,%9},{%0,%1,%2,%3};\n"
        : "+f"(c[0]), "+f"(c[1]), "+f"(c[2]), "+f"(c[3])
        : "r"(a[0]), "r"(a[1]), "r"(a[2]), "r"(a[3]), "r"(b[0]), "r"(b[1]));
}

__device__ __forceinline__ void cp16(uint32_t smem_addr, const void* gptr)
{
    asm volatile("cp.async.cg.shared.global [%0], [%1], 16;"
                 :: "r"(smem_addr), "l"(gptr));
}

__device__ __forceinline__ float sigf(float x) { return 1.f / (1.f + __expf(-x)); }

// ---------------------------------------------------------------------------
__global__ void find_cells_kernel(const float* __restrict__ fa,
                                  int* __restrict__ cx, int* __restrict__ cy,
                                  int* __restrict__ cmap)
{
    if (threadIdx.x == 0 && blockIdx.x == 0) {
        for (int i = 0; i < 64; i++) cmap[i] = -1;
        int k = 0;
        for (int i = 0; i < 8; i++)
            for (int j = 0; j < 8; j++)
                if (fa[i * 8 + j] > 0.5f) { cx[k] = i; cy[k] = j; cmap[i * 8 + j] = k; k++; }
    }
}

// W2p[n][t] = tf32(sum_c wih2[n][c]*e2w[c][t]) ; b2p[n] = bih2[n] + wih2[n].e2b
__global__ void compose_w2_kernel(const float* __restrict__ wih2,
                                  const float* __restrict__ e2w,
                                  const float* __restrict__ e2b,
                                  const float* __restrict__ bih2,
                                  float* __restrict__ W2p, float* __restrict__ b2p)
{
    const int n = blockIdx.x;      // 0..767
    const int t = threadIdx.x;     // 0..63
    float s = 0.f;
    for (int c = 0; c < 256; c++)
        s += wih2[n * 256 + c] * e2w[c * 64 + t];
    W2p[n * 64 + t] = __uint_as_float(f2tf32(s));
    if (t == 0) {
        float sb = 0.f;
        for (int c = 0; c < 256; c++) sb += wih2[n * 256 + c] * e2b[c];
        b2p[n] = bih2[n] + sb;
    }
}

// dst = tf32-rna(src), vectorized
__global__ void cvt_tf32_kernel(const float* __restrict__ s, float* __restrict__ d, int n4)
{
    const int i = blockIdx.x * blockDim.x + threadIdx.x;
    if (i >= n4) return;
    const float4 v = reinterpret_cast<const float4*>(s)[i];
    uint4 u;
    u.x = f2tf32(v.x); u.y = f2tf32(v.y); u.z = f2tf32(v.z); u.w = f2tf32(v.w);
    reinterpret_cast<uint4*>(d)[i] = u;
}

// [whh1;whh2] -> tf32-rounded concat ; [bhh1;bhh2] exact concat
__global__ void concat_whh_kernel(const float* __restrict__ w1, const float* __restrict__ w2,
                                  const float* __restrict__ b1, const float* __restrict__ b2,
                                  float* __restrict__ w12, float* __restrict__ b12)
{
    const int i = blockIdx.x * blockDim.x + threadIdx.x;   // over 1536*64
    if (i < 1536 * 64) {
        const int e = i * 4, row = e >> 8, col = e & 255;
        const float* src = (row < 768) ? (w1 + row * 256 + col) : (w2 + (row - 768) * 256 + col);
        const float4 v = *reinterpret_cast<const float4*>(src);
        uint4 u;
        u.x = f2tf32(v.x); u.y = f2tf32(v.y); u.z = f2tf32(v.z); u.w = f2tf32(v.w);
        reinterpret_cast<uint4*>(w12)[i] = u;
    }
    if (i < 1536) b12[i] = (i < 768) ? b1[i] : b2[i - 768];
}

// ---------------------------------------------------------------------------
// cp.async 3-stage TF32 GEMM-NT: C[z](M,N)=A[z](M,K)@Bw[z](N,K)^T (+bias)
// Tile 128x128x16, 8 warps (2m x 4n), warp 64x32. Inputs pre-tf32-rounded.
//   AMODE 0: normal A (lda).  AMODE 1: A = patch gather from x.
// Dynamic smem: 3 stages * (A 128x20 + B 128x20) u32 = 61440 B.
#define CAS 3
#define ROWU 20
#define STG_U (128 * ROWU)

template<int AMODE>
__global__ __launch_bounds__(256)
void gemm_ca(const float* __restrict__ A, const float* __restrict__ Bw,
             const float* __restrict__ bias, float* __restrict__ C,
             int N, int K, int lda, int ldb,
             long long sAz, long long sBz, long long sCz,
             const int* __restrict__ cxs, const int* __restrict__ cys)
{
    extern __shared__ uint32_t sm[];
    const uint32_t smBase = (uint32_t)__cvta_generic_to_shared(sm);

    const int bm = blockIdx.y * 128;
    const int bn = blockIdx.x * 128;
    int cellBase = 0;
    if (AMODE == 1) cellBase = cxs[blockIdx.z] * 512 + cys[blockIdx.z] * 8;
    if (AMODE == 0) A += (long long)blockIdx.z * sAz;
    Bw += (long long)blockIdx.z * sBz;
    C  += (long long)blockIdx.z * sCz;

    const int tid  = threadIdx.x;
    const int lane = tid & 31;
    const int wid  = tid >> 5;
    const int wm   = wid >> 2;           // 0..1
    const int wn   = wid & 3;            // 0..3
    const int g    = lane >> 2;
    const int t    = lane & 3;
    const int lr   = tid >> 1;           // 0..127
    const int lk   = (tid & 1) * 8;      // 0 / 8

    float acc[4][4][4];
#pragma unroll
    for (int i = 0; i < 4; i++)
#pragma unroll
        for (int j = 0; j < 4; j++)
#pragma unroll
            for (int q = 0; q < 4; q++) acc[i][j][q] = 0.f;

    auto issue = [&](int stg, int k0) {
        const float* ap;
        if (AMODE == 0) ap = A + (long long)(bm + lr) * lda + k0 + lk;
        else { const int tt = k0 + lk;      // tt % 8 == 0
               ap = A + (long long)(bm + lr) * 4096 + cellBase + ((tt >> 3) << 6); }
        const uint32_t da = smBase + 4u * (stg * STG_U + lr * ROWU + lk);
        cp16(da,      ap);
        cp16(da + 16, ap + 4);
        const float* bp = Bw + (long long)(bn + lr) * ldb + k0 + lk;
        const uint32_t db = smBase + 4u * (CAS * STG_U + stg * STG_U + lr * ROWU + lk);
        cp16(db,      bp);
        cp16(db + 16, bp + 4);
    };

    const int nIter = K >> 4;
#pragma unroll
    for (int s = 0; s < CAS - 1; s++) {
        if (s < nIter) issue(s, s * 16);
        asm volatile("cp.async.commit_group;");
    }

    for (int it = 0; it < nIter; it++) {
        const int cur = it % CAS;
        asm volatile("cp.async.wait_group %0;" :: "n"(CAS - 2));
        __syncthreads();

        const uint32_t* Ab = sm + cur * STG_U;
        const uint32_t* Bb = sm + CAS * STG_U + cur * STG_U;
#pragma unroll
        for (int kk = 0; kk < 16; kk += 8) {
            uint32_t af[4][4], bf[4][2];
#pragma unroll
            for (int i = 0; i < 4; i++) {
                const int m = wm * 64 + i * 16;
                af[i][0] = Ab[(m + g) * ROWU + kk + t];
                af[i][1] = Ab[(m + 8 + g) * ROWU + kk + t];
                af[i][2] = Ab[(m + g) * ROWU + kk + t + 4];
                af[i][3] = Ab[(m + 8 + g) * ROWU + kk + t + 4];
            }
#pragma unroll
            for (int j = 0; j < 4; j++) {
                const int n = wn * 32 + j * 8;
                bf[j][0] = Bb[(n + g) * ROWU + kk + t];
                bf[j][1] = Bb[(n + g) * ROWU + kk + t + 4];
            }
#pragma unroll
            for (int i = 0; i < 4; i++)
#pragma unroll
                for (int j = 0; j < 4; j++) mma_tf32(acc[i][j], af[i], bf[j]);
        }
        const int nk = it + CAS - 1;
        if (nk < nIter) issue(nk % CAS, nk * 16);
        asm volatile("cp.async.commit_group;");
    }

#pragma unroll
    for (int i = 0; i < 4; i++) {
        const int row0 = bm + wm * 64 + i * 16 + g;
#pragma unroll
        for (int j = 0; j < 4; j++) {
            const int col = bn + wn * 32 + j * 8 + 2 * t;
            float bz0 = 0.f, bz1 = 0.f;
            if (bias) { bz0 = __ldg(&bias[col]); bz1 = __ldg(&bias[col + 1]); }
            *reinterpret_cast<float2*>(&C[(long long)row0 * N + col]) =
                make_float2(acc[i][j][0] + bz0, acc[i][j][1] + bz1);
            *reinterpret_cast<float2*>(&C[(long long)(row0 + 8) * N + col]) =
                make_float2(acc[i][j][2] + bz0, acc[i][j][3] + bz1);
        }
    }
}

// ---------------------------------------------------------------------------
// R3 register-path GEMM (kept for o1/o2; A = exact fp32 from out).
template<int NT>
__global__ __launch_bounds__(256)
void gemm_tc(const float* __restrict__ A, const float* __restrict__ Bw,
             const float* __restrict__ bias, float* __restrict__ C,
             int M, int N, int K, int lda, int ldb,
             long long sAz, long long sBz, long long sCz)
{
    constexpr int WN  = (NT == 128) ? 4 : 2;
    constexpr int MF  = (NT == 128) ? 4 : 2;
    constexpr int NF  = 4;
    constexpr int WMS = MF * 16;
    constexpr int BLD = (NT == 128) ? 8 : 4;

    __shared__ uint32_t As[2][128][20];
    __shared__ uint32_t Bs[2][NT][20];

    const int bm = blockIdx.y * 128;
    const int bn = blockIdx.x * NT;
    A += (long long)blockIdx.z * sAz;
    Bw += (long long)blockIdx.z * sBz;
    C  += (long long)blockIdx.z * sCz;

    const int tid  = threadIdx.x;
    const int lane = tid & 31;
    const int wid  = tid >> 5;
    const int wm   = wid / WN;
    const int wn   = wid % WN;
    const int g    = lane >> 2;
    const int t    = lane & 3;
    const int ar   = tid >> 1;
    const int ac   = (tid & 1) * 8;
    const int br   = (NT == 128) ? (tid >> 1) : (tid >> 2);
    const int bc   = (NT == 128) ? (tid & 1) * 8 : (tid & 3) * 4;

    float acc[MF][NF][4];
#pragma unroll
    for (int i = 0; i < MF; i++)
#pragma unroll
        for (int j = 0; j < NF; j++)
#pragma unroll
            for (int q = 0; q < 4; q++) acc[i][j][q] = 0.f;

    float a_pref[8], b_pref[BLD];
    {
        const float* ap = A + (long long)(bm + ar) * lda + ac;
        const float4 v0 = *reinterpret_cast<const float4*>(ap);
        const float4 v1 = *reinterpret_cast<const float4*>(ap + 4);
        a_pref[0]=v0.x; a_pref[1]=v0.y; a_pref[2]=v0.z; a_pref[3]=v0.w;
        a_pref[4]=v1.x; a_pref[5]=v1.y; a_pref[6]=v1.z; a_pref[7]=v1.w;
        const float* bp = Bw + (long long)(bn + br) * ldb + bc;
        const float4 w0 = *reinterpret_cast<const float4*>(bp);
        b_pref[0]=w0.x; b_pref[1]=w0.y; b_pref[2]=w0.z; b_pref[3]=w0.w;
        if (BLD == 8) {
            const float4 w1 = *reinterpret_cast<const float4*>(bp + 4);
            b_pref[4]=w1.x; b_pref[5]=w1.y; b_pref[6]=w1.z; b_pref[7]=w1.w;
        }
    }
#pragma unroll
    for (int q = 0; q < 8; q++)   As[0][ar][ac + q] = f2tf32(a_pref[q]);
#pragma unroll
    for (int q = 0; q < BLD; q++) Bs[0][br][bc + q] = f2tf32(b_pref[q]);
    __syncthreads();

    const int nIter = K >> 4;
    for (int it = 0; it < nIter; it++) {
        const int cur = it & 1;
        const bool more = (it + 1 < nIter);
        if (more) {
            const int k0 = (it + 1) * 16;
            const float* ap = A + (long long)(bm + ar) * lda + k0 + ac;
            const float4 v0 = *reinterpret_cast<const float4*>(ap);
            const float4 v1 = *reinterpret_cast<const float4*>(ap + 4);
            a_pref[0]=v0.x; a_pref[1]=v0.y; a_pref[2]=v0.z; a_pref[3]=v0.w;
            a_pref[4]=v1.x; a_pref[5]=v1.y; a_pref[6]=v1.z; a_pref[7]=v1.w;
            const float* bp = Bw + (long long)(bn + br) * ldb + k0 + bc;
            const float4 w0 = *reinterpret_cast<const float4*>(bp);
            b_pref[0]=w0.x; b_pref[1]=w0.y; b_pref[2]=w0.z; b_pref[3]=w0.w;
            if (BLD == 8) {
                const float4 w1 = *reinterpret_cast<const float4*>(bp + 4);
                b_pref[4]=w1.x; b_pref[5]=w1.y; b_pref[6]=w1.z; b_pref[7]=w1.w;
            }
        }
#pragma unroll
        for (int kk = 0; kk < 16; kk += 8) {
            uint32_t af[MF][4], bf[NF][2];
#pragma unroll
            for (int i = 0; i < MF; i++) {
                const int m = wm * WMS + i * 16;
                af[i][0] = As[cur][m + g][kk + t];
                af[i][1] = As[cur][m + 8 + g][kk + t];
                af[i][2] = As[cur][m + g][kk + t + 4];
                af[i][3] = As[cur][m + 8 + g][kk + t + 4];
            }
#pragma unroll
            for (int j = 0; j < NF; j++) {
                const int n = wn * 32 + j * 8;
                bf[j][0] = Bs[cur][n + g][kk + t];
                bf[j][1] = Bs[cur][n + g][kk + t + 4];
            }
#pragma unroll
            for (int i = 0; i < MF; i++)
#pragma unroll
                for (int j = 0; j < NF; j++) mma_tf32(acc[i][j], af[i], bf[j]);
        }
        if (more) {
            const int nxt = cur ^ 1;
#pragma unroll
            for (int q = 0; q < 8; q++)   As[nxt][ar][ac + q] = f2tf32(a_pref[q]);
#pragma unroll
            for (int q = 0; q < BLD; q++) Bs[nxt][br][bc + q] = f2tf32(b_pref[q]);
            __syncthreads();
        }
    }

#pragma unroll
    for (int i = 0; i < MF; i++) {
        const int row0 = bm + wm * WMS + i * 16 + g;
#pragma unroll
        for (int j = 0; j < NF; j++) {
            const int col = bn + wn * 32 + j * 8 + 2 * t;
            float bz0 = 0.f, bz1 = 0.f;
            if (bias) { bz0 = __ldg(&bias[col]); bz1 = __ldg(&bias[col + 1]); }
            *reinterpret_cast<float2*>(&C[(long long)row0 * N + col]) =
                make_float2(acc[i][j][0] + bz0, acc[i][j][1] + bz1);
            *reinterpret_cast<float2*>(&C[(long long)(row0 + 8) * N + col]) =
                make_float2(acc[i][j][2] + bz0, acc[i][j][3] + bz1);
        }
    }
}

// ---------------------------------------------------------------------------
// x1 = tf32(sum of 4 split-K partials + bias)
__global__ void reduce_x1_kernel(const float* __restrict__ P, const float* __restrict__ bias,
                                 float* __restrict__ x1, int n4)
{
    const int idx = blockIdx.x * blockDim.x + threadIdx.x;
    if (idx >= n4) return;
    const float4 p0 = *reinterpret_cast<const float4*>(P + (size_t)0 * BSZ * 256 + idx * 4);
    const float4 p1 = *reinterpret_cast<const float4*>(P + (size_t)1 * BSZ * 256 + idx * 4);
    const float4 p2 = *reinterpret_cast<const float4*>(P + (size_t)2 * BSZ * 256 + idx * 4);
    const float4 p3 = *reinterpret_cast<const float4*>(P + (size_t)3 * BSZ * 256 + idx * 4);
    const int j0 = (idx * 4) & 255;
    const float4 b = *reinterpret_cast<const float4*>(bias + j0);
    uint4 r;
    r.x = f2tf32(p0.x + p1.x + p2.x + p3.x + b.x);
    r.y = f2tf32(p0.y + p1.y + p2.y + p3.y + b.y);
    r.z = f2tf32(p0.z + p1.z + p2.z + p3.z + b.z);
    r.w = f2tf32(p0.w + p1.w + p2.w + p3.w + b.w);
    *reinterpret_cast<uint4*>(x1 + idx * 4) = r;
}

// ---------------------------------------------------------------------------
__global__ void gru_elem_kernel(const float* __restrict__ gi, const float* __restrict__ gh,
                                const float* __restrict__ h0, float* __restrict__ hout,
                                int n4, long long giZ, long long hoZ, int ghStride)
{
    const long long z = blockIdx.z;
    const int idx = blockIdx.x * blockDim.x + threadIdx.x;   // over B*64
    if (idx >= n4) return;
    const int b = idx >> 6;
    const int j = (idx & 63) * 4;
    const float* g = gi + z * giZ + (long long)b * 768;
    const float* q = gh + (long long)b * ghStride;
    const float4 ir = *reinterpret_cast<const float4*>(g + j);
    const float4 iz = *reinterpret_cast<const float4*>(g + 256 + j);
    const float4 in = *reinterpret_cast<const float4*>(g + 512 + j);
    const float4 hr = *reinterpret_cast<const float4*>(q + j);
    const float4 hz = *reinterpret_cast<const float4*>(q + 256 + j);
    const float4 hn = *reinterpret_cast<const float4*>(q + 512 + j);
    const float4 hh = *reinterpret_cast<const float4*>(h0 + (long long)b * 256 + j);
    float4 r;
    { const float rr = sigf(ir.x + hr.x), zz = sigf(iz.x + hz.x);
      r.x = (1.f - zz) * tanhf(in.x + rr * hn.x) + zz * hh.x; }
    { const float rr = sigf(ir.y + hr.y), zz = sigf(iz.y + hz.y);
      r.y = (1.f - zz) * tanhf(in.y + rr * hn.y) + zz * hh.y; }
    { const float rr = sigf(ir.z + hr.z), zz = sigf(iz.z + hz.z);
      r.z = (1.f - zz) * tanhf(in.z + rr * hn.z) + zz * hh.z; }
    { const float rr = sigf(ir.w + hr.w), zz = sigf(iz.w + hz.w);
      r.w = (1.f - zz) * tanhf(in.w + rr * hn.w) + zz * hh.w; }
    *reinterpret_cast<float4*>(hout + z * hoZ + (long long)b * 256 + j) = r;
}

// ---------------------------------------------------------------------------
__global__ void assemble_y_kernel(const float* __restrict__ o1, const float* __restrict__ o2,
                                  const int* __restrict__ cmap, float* __restrict__ y, int n4)
{
    const int idx = blockIdx.x * blockDim.x + threadIdx.x;   // over B*1024
    if (idx >= n4) return;
    const int b   = idx >> 10;
    const int rem = idx & 1023;
    const int i   = rem >> 4;
    const int j0  = (rem & 15) * 4;
    const float v = __ldg(&o1[b * 64 + i]);
    float4 r = make_float4(v, v, v, v);
    const int k = cmap[(i >> 3) * 8 + (j0 >> 3)];
    if (k >= 0) {
        const int t = (i & 7) * 8 + (j0 & 7);
        const float4 a = *reinterpret_cast<const float4*>(o2 + ((long long)k * BSZ + b) * 64 + t);
        r.x += a.x; r.y += a.y; r.z += a.z; r.w += a.w;
    }
    *reinterpret_cast<float4*>(y + (long long)idx * 4) = r;
}

// ---------------------------------------------------------------------------
extern "C" void kernel_launch(void* const* d_in, const int* in_sizes, int n_in,
                              void* d_out, int out_size)
{
    const float* x    = (const float*)d_in[0];
    const float* h    = (const float*)d_in[1];
    const float* fa   = (const float*)d_in[2];
    const float* e1w  = (const float*)d_in[3];
    const float* e1b  = (const float*)d_in[4];
    const float* wih1 = (const float*)d_in[5];
    const float* whh1 = (const float*)d_in[6];
    const float* bih1 = (const float*)d_in[7];
    const float* bhh1 = (const float*)d_in[8];
    const float* o1w  = (const float*)d_in[9];
    const float* o1b  = (const float*)d_in[10];
    const float* e2w  = (const float*)d_in[11];
    const float* e2b  = (const float*)d_in[12];
    const float* wih2 = (const float*)d_in[13];
    const float* whh2 = (const float*)d_in[14];
    const float* bih2 = (const float*)d_in[15];
    const float* bhh2 = (const float*)d_in[16];
    const float* o2w  = (const float*)d_in[17];
    const float* o2b  = (const float*)d_in[18];
    float* out = (float*)d_out;

    const int B = in_sizes[0] / 4096;                  // 2048
    const long long YOFF = (long long)B * 4096;
    int Kc = (int)(((long long)out_size - YOFF) / ((long long)B * 256)) - 1;
    if (Kc < 0) Kc = 0;
    if (Kc > MAXK) Kc = MAXK;

    float *p_xc, *p_hc, *p_e1c, *p_wi1c, *p_whhc, *p_bhh, *p_xp, *p_x1,
          *p_gh12, *p_gi1, *p_gi2, *p_o1, *p_o2, *p_w2p, *p_b2p;
    int *p_cx, *p_cy, *p_cmap;
    cudaGetSymbolAddress((void**)&p_xc,   d_xc);
    cudaGetSymbolAddress((void**)&p_hc,   d_hc);
    cudaGetSymbolAddress((void**)&p_e1c,  d_e1c);
    cudaGetSymbolAddress((void**)&p_wi1c, d_wi1c);
    cudaGetSymbolAddress((void**)&p_whhc, d_whhc);
    cudaGetSymbolAddress((void**)&p_bhh,  d_bhh);
    cudaGetSymbolAddress((void**)&p_xp,   d_xp);
    cudaGetSymbolAddress((void**)&p_x1,   d_x1);
    cudaGetSymbolAddress((void**)&p_gh12, d_gh12);
    cudaGetSymbolAddress((void**)&p_gi1,  d_gi1);
    cudaGetSymbolAddress((void**)&p_gi2,  d_gi2);
    cudaGetSymbolAddress((void**)&p_o1,   d_o1);
    cudaGetSymbolAddress((void**)&p_o2,   d_o2);
    cudaGetSymbolAddress((void**)&p_w2p,  d_w2p);
    cudaGetSymbolAddress((void**)&p_b2p,  d_b2p);
    cudaGetSymbolAddress((void**)&p_cx,   d_cx);
    cudaGetSymbolAddress((void**)&p_cy,   d_cy);
    cudaGetSymbolAddress((void**)&p_cmap, d_cmap);

    // allow 60KB dynamic smem for the cp.async GEMMs
    cudaFuncSetAttribute(gemm_ca<0>, cudaFuncAttributeMaxDynamicSharedMemorySize, 61440);
    cudaFuncSetAttribute(gemm_ca<1>, cudaFuncAttributeMaxDynamicSharedMemorySize, 61440);
    const int SMB = 61440;

    float* yh0 = out + YOFF;
    float* yh2 = out + YOFF + (long long)B * 256;

    find_cells_kernel<<<1, 32>>>(fa, p_cx, p_cy, p_cmap);
    compose_w2_kernel<<<768, 64>>>(wih2, e2w, e2b, bih2, p_w2p, p_b2p);

    // pre-round big-GEMM inputs to tf32 (rna) so cp.async raw loads == R3 math
    cvt_tf32_kernel<<<(B * 1024 + 255) / 256, 256>>>(x, p_xc, B * 1024);            // B*4096
    cvt_tf32_kernel<<<(B * 64 + 255) / 256, 256>>>(h, p_hc, B * 64);                // B*256
    cvt_tf32_kernel<<<(256 * 1024 + 255) / 256, 256>>>(e1w, p_e1c, 256 * 1024);     // 256*4096
    cvt_tf32_kernel<<<(768 * 64 + 255) / 256, 256>>>(wih1, p_wi1c, 768 * 64);       // 768*256
    concat_whh_kernel<<<(1536 * 64 + 255) / 256, 256>>>(whh1, whh2, bhh1, bhh2, p_whhc, p_bhh);

    // x1 split-K=4 partials (N=256, K slab=1024) + rounded reduce
    gemm_ca<0><<<dim3(2, B / 128, 4), 256, SMB>>>(p_xc, p_e1c, nullptr, p_xp,
                                                  256, 1024, 4096, 4096,
                                                  1024, 1024, (long long)B * 256,
                                                  nullptr, nullptr);
    reduce_x1_kernel<<<(B * 64 + 255) / 256, 256>>>(p_xp, e1b, p_x1, B * 64);

    // gh12 = h @ [whh1;whh2]^T + [bhh1;bhh2]  (N=1536, K=256)
    gemm_ca<0><<<dim3(12, B / 128), 256, SMB>>>(p_hc, p_whhc, p_bhh, p_gh12,
                                                1536, 256, 256, 256, 0, 0, 0,
                                                nullptr, nullptr);
    // gi1 = x1 @ wih1^T + bih1  (N=768, K=256)
    gemm_ca<0><<<dim3(6, B / 128), 256, SMB>>>(p_x1, p_wi1c, bih1, p_gi1,
                                               768, 256, 256, 256, 0, 0, 0,
                                               nullptr, nullptr);
    // h1 -> out y_h[0]
    gru_elem_kernel<<<dim3((B * 64 + 255) / 256, 1, 1), 256>>>(p_gi1, p_gh12, h, yh0,
                                                               B * 64, 0, 0, 1536);
    // o1 = h1 @ o1w^T + b  (N=64, K=256; exact-A register path)
    gemm_tc<64><<<dim3(1, B / 128), 256>>>(yh0, o1w, o1b, p_o1,
                                           B, 64, 256, 256, 256, 0, 0, 0);

    if (Kc > 0) {
        // gi2[k] = patch[k] @ W2p^T + b2p  (gather A from xc; N=768, K=64)
        gemm_ca<1><<<dim3(6, B / 128, Kc), 256, SMB>>>(p_xc, p_w2p, p_b2p, p_gi2,
                                                       768, 64, 64, 64,
                                                       0, 0, (long long)B * 768,
                                                       p_cx, p_cy);
        // h2[k] -> out y_h[1+k]
        gru_elem_kernel<<<dim3((B * 64 + 255) / 256, 1, Kc), 256>>>(p_gi2, p_gh12 + 768, h, yh2,
                                                                    B * 64,
                                                                    (long long)B * 768,
                                                                    (long long)B * 256, 1536);
        // o2[k] = h2[k] @ o2w^T + b  (N=64, K=256)
        gemm_tc<64><<<dim3(1, B / 128, Kc), 256>>>(yh2, o2w, o2b, p_o2,
                                                   B, 64, 256, 256, 256,
                                                   (long long)B * 256, 0, (long long)B * 64);
    }
    // y = bcast(o1) + scatter(o2)
    assemble_y_kernel<<<(B * 1024 + 255) / 256, 256>>>(p_o1, p_o2, p_cmap, out, B * 1024);
}

// round 6
// speedup vs baseline: 1.9975x; 1.0715x over previous
#include <cuda_runtime.h>
#include <cuda_fp16.h>
#include <cstdint>

// ---------------------------------------------------------------------------
// FocDecoderRNN — cp.async TF32 engine everywhere; fp16 gi buffers; merged
// o1/o2 GEMM; GRU dual-writes exact h (out) + tf32-rounded h (scratch).
// ---------------------------------------------------------------------------

#define BSZ  2048
#define MAXK 64

__device__ float  d_xc  [(size_t)BSZ * 4096];     // tf32-rounded x
__device__ float  d_hc  [BSZ * 256];              // tf32-rounded h
__device__ float  d_e1c [256 * 4096];             // tf32-rounded embed1_w
__device__ float  d_wi1c[768 * 256];              // tf32-rounded w_ih1
__device__ float  d_whhc[1536 * 256];             // tf32-rounded [whh1;whh2]
__device__ float  d_bhh [1536];
__device__ float  d_o1wc[64 * 256];               // tf32-rounded out1_w
__device__ float  d_o2wc[64 * 256];               // tf32-rounded out2_w
__device__ float  d_xp  [4 * BSZ * 256];
__device__ float  d_x1  [BSZ * 256];              // tf32-rounded
__device__ float  d_gh12[(size_t)BSZ * 1536];
__device__ __half d_gi1h[BSZ * 768];
__device__ __half d_gi2h[(size_t)MAXK * BSZ * 768];
__device__ float  d_hr  [(size_t)(MAXK + 1) * BSZ * 256];  // tf32-rounded h slots
__device__ float  d_o   [(size_t)(MAXK + 1) * BSZ * 64];   // o1 slot0, o2 slots 1..K
__device__ float  d_w2p [768 * 64];
__device__ float  d_b2p [768];
__device__ int    d_cx[MAXK], d_cy[MAXK], d_cmap[64];

// ---------------------------------------------------------------------------
__device__ __forceinline__ uint32_t f2tf32(float x)
{
    uint32_t u;
    asm("cvt.rna.tf32.f32 %0, %1;" : "=r"(u) : "f"(x));
    return u;
}

__device__ __forceinline__ void mma_tf32(float c[4], const uint32_t a[4], const uint32_t b[2])
{
    asm volatile(
        "mma.sync.aligned.m16n8k8.row.col.f32.tf32.tf32.f32 "
        "{%0,%1,%2,%3},{%4,%5,%6,%7},{%8,%9},{%0,%1,%2,%3};\n"
        : "+f"(c[0]), "+f"(c[1]), "+f"(c[2]), "+f"(c[3])
        : "r"(a[0]), "r"(a[1]), "r"(a[2]), "r"(a[3]), "r"(b[0]), "r"(b[1]));
}

__device__ __forceinline__ void cp16(uint32_t smem_addr, const void* gptr)
{
    asm volatile("cp.async.cg.shared.global [%0], [%1], 16;"
                 :: "r"(smem_addr), "l"(gptr));
}

__device__ __forceinline__ float sigf(float x) { return 1.f / (1.f + __expf(-x)); }

// ---------------------------------------------------------------------------
__global__ void find_cells_kernel(const float* __restrict__ fa,
                                  int* __restrict__ cx, int* __restrict__ cy,
                                  int* __restrict__ cmap)
{
    if (threadIdx.x == 0 && blockIdx.x == 0) {
        for (int i = 0; i < 64; i++) cmap[i] = -1;
        int k = 0;
        for (int i = 0; i < 8; i++)
            for (int j = 0; j < 8; j++)
                if (fa[i * 8 + j] > 0.5f) { cx[k] = i; cy[k] = j; cmap[i * 8 + j] = k; k++; }
    }
}

__global__ void compose_w2_kernel(const float* __restrict__ wih2,
                                  const float* __restrict__ e2w,
                                  const float* __restrict__ e2b,
                                  const float* __restrict__ bih2,
                                  float* __restrict__ W2p, float* __restrict__ b2p)
{
    const int n = blockIdx.x;
    const int t = threadIdx.x;
    float s = 0.f;
    for (int c = 0; c < 256; c++)
        s += wih2[n * 256 + c] * e2w[c * 64 + t];
    W2p[n * 64 + t] = __uint_as_float(f2tf32(s));
    if (t == 0) {
        float sb = 0.f;
        for (int c = 0; c < 256; c++) sb += wih2[n * 256 + c] * e2b[c];
        b2p[n] = bih2[n] + sb;
    }
}

__global__ void cvt_tf32_kernel(const float* __restrict__ s, float* __restrict__ d, int n4)
{
    const int i = blockIdx.x * blockDim.x + threadIdx.x;
    if (i >= n4) return;
    const float4 v = reinterpret_cast<const float4*>(s)[i];
    uint4 u;
    u.x = f2tf32(v.x); u.y = f2tf32(v.y); u.z = f2tf32(v.z); u.w = f2tf32(v.w);
    reinterpret_cast<uint4*>(d)[i] = u;
}

__global__ void concat_whh_kernel(const float* __restrict__ w1, const float* __restrict__ w2,
                                  const float* __restrict__ b1, const float* __restrict__ b2,
                                  float* __restrict__ w12, float* __restrict__ b12)
{
    const int i = blockIdx.x * blockDim.x + threadIdx.x;
    if (i < 1536 * 64) {
        const int e = i * 4, row = e >> 8, col = e & 255;
        const float* src = (row < 768) ? (w1 + row * 256 + col) : (w2 + (row - 768) * 256 + col);
        const float4 v = *reinterpret_cast<const float4*>(src);
        uint4 u;
        u.x = f2tf32(v.x); u.y = f2tf32(v.y); u.z = f2tf32(v.z); u.w = f2tf32(v.w);
        reinterpret_cast<uint4*>(w12)[i] = u;
    }
    if (i < 1536) b12[i] = (i < 768) ? b1[i] : b2[i - 768];
}

// ---------------------------------------------------------------------------
// cp.async 3-stage TF32 GEMM-NT. Tile 128 x NT x 16. Inputs pre-tf32-rounded.
//   AMODE 0: normal A (lda, sAz).  AMODE 1: A = patch gather from x.
//   HOUT  0: fp32 C.             1: fp16 C.
//   OSEL  1: z>0 uses Bw2/bias2 (merged o1/o2 GEMM).
#define CAS  3
#define ROWU 20

template<int AMODE, int NT, int HOUT, int OSEL>
__global__ __launch_bounds__(256)
void gemm_ca(const float* __restrict__ A,
             const float* __restrict__ Bw, const float* __restrict__ Bw2,
             const float* __restrict__ bias, const float* __restrict__ bias2,
             void* __restrict__ Cv,
             int N, int K, int lda, int ldb,
             long long sAz, long long sBz, long long sCz,
             const int* __restrict__ cxs, const int* __restrict__ cys)
{
    constexpr int STG_A = 128 * ROWU;
    constexpr int STG_B = NT * ROWU;
    constexpr int WNW   = (NT == 128) ? 4 : 2;   // warps along n
    constexpr int MF    = (NT == 128) ? 4 : 2;   // 16-row frags per warp

    extern __shared__ uint32_t sm[];
    const uint32_t smBase = (uint32_t)__cvta_generic_to_shared(sm);

    const int bm = blockIdx.y * 128;
    const int bn = blockIdx.x * NT;
    int cellBase = 0;
    if (AMODE == 1) cellBase = cxs[blockIdx.z] * 512 + cys[blockIdx.z] * 8;
    if (AMODE == 0) A += (long long)blockIdx.z * sAz;
    if (OSEL == 1 && blockIdx.z > 0) { Bw = Bw2; bias = bias2; }
    Bw += (long long)blockIdx.z * sBz;

    const int tid  = threadIdx.x;
    const int lane = tid & 31;
    const int wid  = tid >> 5;
    const int wm   = wid / WNW;
    const int wn   = wid % WNW;
    const int g    = lane >> 2;
    const int t    = lane & 3;
    const int lr   = tid >> 1;             // A row 0..127
    const int lk   = (tid & 1) * 8;
    const int br   = (NT == 128) ? (tid >> 1) : (tid >> 2);
    const int bc   = (NT == 128) ? (tid & 1) * 8 : (tid & 3) * 4;

    float acc[MF][4][4];
#pragma unroll
    for (int i = 0; i < MF; i++)
#pragma unroll
        for (int j = 0; j < 4; j++)
#pragma unroll
            for (int q = 0; q < 4; q++) acc[i][j][q] = 0.f;

    auto issue = [&](int stg, int k0) {
        const float* ap;
        if (AMODE == 0) ap = A + (long long)(bm + lr) * lda + k0 + lk;
        else { const int tt = k0 + lk;
               ap = A + (long long)(bm + lr) * 4096 + cellBase + ((tt >> 3) << 6); }
        const uint32_t da = smBase + 4u * (stg * STG_A + lr * ROWU + lk);
        cp16(da,      ap);
        cp16(da + 16, ap + 4);
        const float* bp = Bw + (long long)(bn + br) * ldb + k0 + bc;
        const uint32_t db = smBase + 4u * (CAS * STG_A + stg * STG_B + br * ROWU + bc);
        cp16(db, bp);
        if (NT == 128) cp16(db + 16, bp + 4);
    };

    const int nIter = K >> 4;
#pragma unroll
    for (int s = 0; s < CAS - 1; s++) {
        if (s < nIter) issue(s, s * 16);
        asm volatile("cp.async.commit_group;");
    }

    for (int it = 0; it < nIter; it++) {
        const int cur = it % CAS;
        asm volatile("cp.async.wait_group %0;" :: "n"(CAS - 2));
        __syncthreads();

        const uint32_t* Ab = sm + cur * STG_A;
        const uint32_t* Bb = sm + CAS * STG_A + cur * STG_B;
#pragma unroll
        for (int kk = 0; kk < 16; kk += 8) {
            uint32_t af[MF][4], bf[4][2];
#pragma unroll
            for (int i = 0; i < MF; i++) {
                const int m = wm * (MF * 16) + i * 16;
                af[i][0] = Ab[(m + g) * ROWU + kk + t];
                af[i][1] = Ab[(m + 8 + g) * ROWU + kk + t];
                af[i][2] = Ab[(m + g) * ROWU + kk + t + 4];
                af[i][3] = Ab[(m + 8 + g) * ROWU + kk + t + 4];
            }
#pragma unroll
            for (int j = 0; j < 4; j++) {
                const int n = wn * 32 + j * 8;
                bf[j][0] = Bb[(n + g) * ROWU + kk + t];
                bf[j][1] = Bb[(n + g) * ROWU + kk + t + 4];
            }
#pragma unroll
            for (int i = 0; i < MF; i++)
#pragma unroll
                for (int j = 0; j < 4; j++) mma_tf32(acc[i][j], af[i], bf[j]);
        }
        const int nk = it + CAS - 1;
        if (nk < nIter) issue(nk % CAS, nk * 16);
        asm volatile("cp.async.commit_group;");
    }

    // ---- epilogue ----
    float* Cf = (float*)Cv;
    __half* Ch = (__half*)Cv;
#pragma unroll
    for (int i = 0; i < MF; i++) {
        const int row0 = bm + wm * (MF * 16) + i * 16 + g;
#pragma unroll
        for (int j = 0; j < 4; j++) {
            const int col = bn + wn * 32 + j * 8 + 2 * t;
            float bz0 = 0.f, bz1 = 0.f;
            if (bias) { bz0 = __ldg(&bias[col]); bz1 = __ldg(&bias[col + 1]); }
            const float v0 = acc[i][j][0] + bz0, v1 = acc[i][j][1] + bz1;
            const float v2 = acc[i][j][2] + bz0, v3 = acc[i][j][3] + bz1;
            if (HOUT == 0) {
                float* C = Cf + (long long)blockIdx.z * sCz;
                *reinterpret_cast<float2*>(&C[(long long)row0 * N + col]) = make_float2(v0, v1);
                *reinterpret_cast<float2*>(&C[(long long)(row0 + 8) * N + col]) = make_float2(v2, v3);
            } else {
                __half* C = Ch + (long long)blockIdx.z * sCz;
                *reinterpret_cast<__half2*>(&C[(long long)row0 * N + col]) =
                    __floats2half2_rn(v0, v1);
                *reinterpret_cast<__half2*>(&C[(long long)(row0 + 8) * N + col]) =
                    __floats2half2_rn(v2, v3);
            }
        }
    }
}

// ---------------------------------------------------------------------------
__global__ void reduce_x1_kernel(const float* __restrict__ P, const float* __restrict__ bias,
                                 float* __restrict__ x1, int n4)
{
    const int idx = blockIdx.x * blockDim.x + threadIdx.x;
    if (idx >= n4) return;
    const float4 p0 = *reinterpret_cast<const float4*>(P + (size_t)0 * BSZ * 256 + idx * 4);
    const float4 p1 = *reinterpret_cast<const float4*>(P + (size_t)1 * BSZ * 256 + idx * 4);
    const float4 p2 = *reinterpret_cast<const float4*>(P + (size_t)2 * BSZ * 256 + idx * 4);
    const float4 p3 = *reinterpret_cast<const float4*>(P + (size_t)3 * BSZ * 256 + idx * 4);
    const int j0 = (idx * 4) & 255;
    const float4 b = *reinterpret_cast<const float4*>(bias + j0);
    uint4 r;
    r.x = f2tf32(p0.x + p1.x + p2.x + p3.x + b.x);
    r.y = f2tf32(p0.y + p1.y + p2.y + p3.y + b.y);
    r.z = f2tf32(p0.z + p1.z + p2.z + p3.z + b.z);
    r.w = f2tf32(p0.w + p1.w + p2.w + p3.w + b.w);
    *reinterpret_cast<uint4*>(x1 + idx * 4) = r;
}

// ---------------------------------------------------------------------------
// GRU from fp16 gi. Dual write: exact h -> hout, tf32-rounded h -> hrnd.
__global__ void gru_elem_h_kernel(const __half* __restrict__ gi, const float* __restrict__ gh,
                                  const float* __restrict__ h0,
                                  float* __restrict__ hout, float* __restrict__ hrnd,
                                  int n4, long long giZ, long long hoZ, int ghStride)
{
    const long long z = blockIdx.z;
    const int idx = blockIdx.x * blockDim.x + threadIdx.x;   // over B*64
    if (idx >= n4) return;
    const int b = idx >> 6;
    const int j = (idx & 63) * 4;
    const __half* g = gi + z * giZ + (long long)b * 768;
    const float* q  = gh + (long long)b * ghStride;

    const float2 ir01 = __half22float2(*reinterpret_cast<const __half2*>(g + j));
    const float2 ir23 = __half22float2(*reinterpret_cast<const __half2*>(g + j + 2));
    const float2 iz01 = __half22float2(*reinterpret_cast<const __half2*>(g + 256 + j));
    const float2 iz23 = __half22float2(*reinterpret_cast<const __half2*>(g + 256 + j + 2));
    const float2 in01 = __half22float2(*reinterpret_cast<const __half2*>(g + 512 + j));
    const float2 in23 = __half22float2(*reinterpret_cast<const __half2*>(g + 512 + j + 2));
    const float4 hr = *reinterpret_cast<const float4*>(q + j);
    const float4 hz = *reinterpret_cast<const float4*>(q + 256 + j);
    const float4 hn = *reinterpret_cast<const float4*>(q + 512 + j);
    const float4 hh = *reinterpret_cast<const float4*>(h0 + (long long)b * 256 + j);

    float4 r;
    { const float rr = sigf(ir01.x + hr.x), zz = sigf(iz01.x + hz.x);
      r.x = (1.f - zz) * tanhf(in01.x + rr * hn.x) + zz * hh.x; }
    { const float rr = sigf(ir01.y + hr.y), zz = sigf(iz01.y + hz.y);
      r.y = (1.f - zz) * tanhf(in01.y + rr * hn.y) + zz * hh.y; }
    { const float rr = sigf(ir23.x + hr.z), zz = sigf(iz23.x + hz.z);
      r.z = (1.f - zz) * tanhf(in23.x + rr * hn.z) + zz * hh.z; }
    { const float rr = sigf(ir23.y + hr.w), zz = sigf(iz23.y + hz.w);
      r.w = (1.f - zz) * tanhf(in23.y + rr * hn.w) + zz * hh.w; }

    const long long off = z * hoZ + (long long)b * 256 + j;
    *reinterpret_cast<float4*>(hout + off) = r;
    uint4 u;
    u.x = f2tf32(r.x); u.y = f2tf32(r.y); u.z = f2tf32(r.z); u.w = f2tf32(r.w);
    *reinterpret_cast<uint4*>(hrnd + off) = u;
}

// ---------------------------------------------------------------------------
__global__ void assemble_y_kernel(const float* __restrict__ o1, const float* __restrict__ o2,
                                  const int* __restrict__ cmap, float* __restrict__ y, int n4)
{
    const int idx = blockIdx.x * blockDim.x + threadIdx.x;   // over B*1024
    if (idx >= n4) return;
    const int b   = idx >> 10;
    const int rem = idx & 1023;
    const int i   = rem >> 4;
    const int j0  = (rem & 15) * 4;
    const float v = __ldg(&o1[b * 64 + i]);
    float4 r = make_float4(v, v, v, v);
    const int k = cmap[(i >> 3) * 8 + (j0 >> 3)];
    if (k >= 0) {
        const int t = (i & 7) * 8 + (j0 & 7);
        const float4 a = *reinterpret_cast<const float4*>(o2 + ((long long)k * BSZ + b) * 64 + t);
        r.x += a.x; r.y += a.y; r.z += a.z; r.w += a.w;
    }
    *reinterpret_cast<float4*>(y + (long long)idx * 4) = r;
}

// ---------------------------------------------------------------------------
extern "C" void kernel_launch(void* const* d_in, const int* in_sizes, int n_in,
                              void* d_out, int out_size)
{
    const float* x    = (const float*)d_in[0];
    const float* h    = (const float*)d_in[1];
    const float* fa   = (const float*)d_in[2];
    const float* e1w  = (const float*)d_in[3];
    const float* e1b  = (const float*)d_in[4];
    const float* wih1 = (const float*)d_in[5];
    const float* whh1 = (const float*)d_in[6];
    const float* bih1 = (const float*)d_in[7];
    const float* bhh1 = (const float*)d_in[8];
    const float* o1w  = (const float*)d_in[9];
    const float* o1b  = (const float*)d_in[10];
    const float* e2w  = (const float*)d_in[11];
    const float* e2b  = (const float*)d_in[12];
    const float* wih2 = (const float*)d_in[13];
    const float* whh2 = (const float*)d_in[14];
    const float* bih2 = (const float*)d_in[15];
    const float* bhh2 = (const float*)d_in[16];
    const float* o2w  = (const float*)d_in[17];
    const float* o2b  = (const float*)d_in[18];
    float* out = (float*)d_out;

    const int B = in_sizes[0] / 4096;                  // 2048
    const long long YOFF = (long long)B * 4096;
    int Kc = (int)(((long long)out_size - YOFF) / ((long long)B * 256)) - 1;
    if (Kc < 0) Kc = 0;
    if (Kc > MAXK) Kc = MAXK;

    float *p_xc, *p_hc, *p_e1c, *p_wi1c, *p_whhc, *p_bhh, *p_o1wc, *p_o2wc,
          *p_xp, *p_x1, *p_gh12, *p_hr, *p_o, *p_w2p, *p_b2p;
    __half *p_gi1h, *p_gi2h;
    int *p_cx, *p_cy, *p_cmap;
    cudaGetSymbolAddress((void**)&p_xc,   d_xc);
    cudaGetSymbolAddress((void**)&p_hc,   d_hc);
    cudaGetSymbolAddress((void**)&p_e1c,  d_e1c);
    cudaGetSymbolAddress((void**)&p_wi1c, d_wi1c);
    cudaGetSymbolAddress((void**)&p_whhc, d_whhc);
    cudaGetSymbolAddress((void**)&p_bhh,  d_bhh);
    cudaGetSymbolAddress((void**)&p_o1wc, d_o1wc);
    cudaGetSymbolAddress((void**)&p_o2wc, d_o2wc);
    cudaGetSymbolAddress((void**)&p_xp,   d_xp);
    cudaGetSymbolAddress((void**)&p_x1,   d_x1);
    cudaGetSymbolAddress((void**)&p_gh12, d_gh12);
    cudaGetSymbolAddress((void**)&p_gi1h, d_gi1h);
    cudaGetSymbolAddress((void**)&p_gi2h, d_gi2h);
    cudaGetSymbolAddress((void**)&p_hr,   d_hr);
    cudaGetSymbolAddress((void**)&p_o,    d_o);
    cudaGetSymbolAddress((void**)&p_w2p,  d_w2p);
    cudaGetSymbolAddress((void**)&p_b2p,  d_b2p);
    cudaGetSymbolAddress((void**)&p_cx,   d_cx);
    cudaGetSymbolAddress((void**)&p_cy,   d_cy);
    cudaGetSymbolAddress((void**)&p_cmap, d_cmap);

    const int SMB128 = 61440;                // 3*(128+128)*20*4
    const int SMB64  = 46080;                // 3*(128+64)*20*4
    cudaFuncSetAttribute((const void*)gemm_ca<0, 128, 0, 0>, cudaFuncAttributeMaxDynamicSharedMemorySize, SMB128);
    cudaFuncSetAttribute((const void*)gemm_ca<0, 128, 1, 0>, cudaFuncAttributeMaxDynamicSharedMemorySize, SMB128);
    cudaFuncSetAttribute((const void*)gemm_ca<1, 128, 1, 0>, cudaFuncAttributeMaxDynamicSharedMemorySize, SMB128);
    cudaFuncSetAttribute((const void*)gemm_ca<0, 64, 0, 1>,  cudaFuncAttributeMaxDynamicSharedMemorySize, SMB64);

    float* yh0 = out + YOFF;
    float* yh2 = out + YOFF + (long long)B * 256;

    find_cells_kernel<<<1, 32>>>(fa, p_cx, p_cy, p_cmap);
    compose_w2_kernel<<<768, 64>>>(wih2, e2w, e2b, bih2, p_w2p, p_b2p);

    // pre-round all cp.async GEMM inputs to tf32 (rna)
    cvt_tf32_kernel<<<(B * 1024 + 255) / 256, 256>>>(x, p_xc, B * 1024);
    cvt_tf32_kernel<<<(B * 64 + 255) / 256, 256>>>(h, p_hc, B * 64);
    cvt_tf32_kernel<<<(256 * 1024 + 255) / 256, 256>>>(e1w, p_e1c, 256 * 1024);
    cvt_tf32_kernel<<<(768 * 64 + 255) / 256, 256>>>(wih1, p_wi1c, 768 * 64);
    cvt_tf32_kernel<<<(64 * 64 + 255) / 256, 256>>>(o1w, p_o1wc, 64 * 64);
    cvt_tf32_kernel<<<(64 * 64 + 255) / 256, 256>>>(o2w, p_o2wc, 64 * 64);
    concat_whh_kernel<<<(1536 * 64 + 255) / 256, 256>>>(whh1, whh2, bhh1, bhh2, p_whhc, p_bhh);

    // x1 split-K=4 partials (N=256, K slab=1024) + rounded reduce
    gemm_ca<0, 128, 0, 0><<<dim3(2, B / 128, 4), 256, SMB128>>>(
        p_xc, p_e1c, nullptr, nullptr, nullptr, p_xp,
        256, 1024, 4096, 4096, 1024, 1024, (long long)B * 256, nullptr, nullptr);
    reduce_x1_kernel<<<(B * 64 + 255) / 256, 256>>>(p_xp, e1b, p_x1, B * 64);

    // gh12 = h @ [whh1;whh2]^T + [bhh1;bhh2]  (N=1536, K=256)
    gemm_ca<0, 128, 0, 0><<<dim3(12, B / 128), 256, SMB128>>>(
        p_hc, p_whhc, nullptr, p_bhh, nullptr, p_gh12,
        1536, 256, 256, 256, 0, 0, 0, nullptr, nullptr);

    // gi1 = x1 @ wih1^T + bih1 -> fp16  (N=768, K=256)
    gemm_ca<0, 128, 1, 0><<<dim3(6, B / 128), 256, SMB128>>>(
        p_x1, p_wi1c, nullptr, bih1, nullptr, p_gi1h,
        768, 256, 256, 256, 0, 0, 0, nullptr, nullptr);

    // h1 -> out y_h[0] (exact) + hr slot0 (rounded)
    gru_elem_h_kernel<<<dim3((B * 64 + 255) / 256, 1, 1), 256>>>(
        p_gi1h, p_gh12, h, yh0, p_hr, B * 64, 0, 0, 1536);

    if (Kc > 0) {
        // gi2[k] = patch[k] @ W2p^T + b2p -> fp16  (gather A; N=768, K=64)
        gemm_ca<1, 128, 1, 0><<<dim3(6, B / 128, Kc), 256, SMB128>>>(
            p_xc, p_w2p, nullptr, p_b2p, nullptr, p_gi2h,
            768, 64, 64, 64, 0, 0, (long long)B * 768, p_cx, p_cy);
        // h2[k] -> out y_h[1+k] (exact) + hr slot 1+k (rounded)
        gru_elem_h_kernel<<<dim3((B * 64 + 255) / 256, 1, Kc), 256>>>(
            p_gi2h, p_gh12 + 768, h, yh2, p_hr + (long long)B * 256,
            B * 64, (long long)B * 768, (long long)B * 256, 1536);
    }

    // merged o GEMM: z=0 -> o1 (o1w), z>=1 -> o2[z-1] (o2w); A = hr slots
    gemm_ca<0, 64, 0, 1><<<dim3(1, B / 128, Kc + 1), 256, SMB64>>>(
        p_hr, p_o1wc, p_o2wc, o1b, o2b, p_o,
        64, 256, 256, 256, (long long)B * 256, 0, (long long)B * 64, nullptr, nullptr);

    // y = bcast(o1) + scatter(o2)
    assemble_y_kernel<<<(B * 1024 + 255) / 256, 256>>>(p_o, p_o + (long long)B * 64,
                                                       p_cmap, out, B * 1024);
}